// round 1
// baseline (speedup 1.0000x reference)
#include <cuda_runtime.h>
#include <stdint.h>

#define NUM_BINS 256
#define NCH 48                       // B*C = 16*3
#define NPIX (1024 * 1024)           // H*W per channel
#define N4 (NPIX / 4)

// Scratch (device globals — allocation-free)
__device__ int           g_hist[NCH * NUM_BINS];
__device__ float         g_cdf[NCH * NUM_BINS];
__device__ unsigned char g_bins[(size_t)NCH * NPIX];   // 48 MiB

// ---------------------------------------------------------------------------
// Kernel 0: zero histogram
// ---------------------------------------------------------------------------
__global__ void zero_hist_kernel() {
    int i = blockIdx.x * blockDim.x + threadIdx.x;
    if (i < NCH * NUM_BINS) g_hist[i] = 0;
}

// ---------------------------------------------------------------------------
// Kernel 1: per-channel histogram + quantized-bin store
//   grid = (blocksPerChan, NCH), block = 256
// ---------------------------------------------------------------------------
__global__ void hist_kernel(const float* __restrict__ x) {
    __shared__ int sh[NUM_BINS];
    const int c = blockIdx.y;

    for (int i = threadIdx.x; i < NUM_BINS; i += blockDim.x) sh[i] = 0;
    __syncthreads();

    const float4* xc = reinterpret_cast<const float4*>(x + (size_t)c * NPIX);
    uchar4*       bc = reinterpret_cast<uchar4*>(g_bins + (size_t)c * NPIX);

    const int stride = gridDim.x * blockDim.x;
    for (int i = blockIdx.x * blockDim.x + threadIdx.x; i < N4; i += stride) {
        float4 v = xc[i];
        // match reference exactly: clip to [0,1], *255 (f32), trunc to int, clip
        int q0 = (int)(fminf(fmaxf(v.x, 0.0f), 1.0f) * 255.0f);
        int q1 = (int)(fminf(fmaxf(v.y, 0.0f), 1.0f) * 255.0f);
        int q2 = (int)(fminf(fmaxf(v.z, 0.0f), 1.0f) * 255.0f);
        int q3 = (int)(fminf(fmaxf(v.w, 0.0f), 1.0f) * 255.0f);
        q0 = min(max(q0, 0), 255);
        q1 = min(max(q1, 0), 255);
        q2 = min(max(q2, 0), 255);
        q3 = min(max(q3, 0), 255);

        atomicAdd(&sh[q0], 1);
        atomicAdd(&sh[q1], 1);
        atomicAdd(&sh[q2], 1);
        atomicAdd(&sh[q3], 1);

        bc[i] = make_uchar4((unsigned char)q0, (unsigned char)q1,
                            (unsigned char)q2, (unsigned char)q3);
    }
    __syncthreads();

    for (int i = threadIdx.x; i < NUM_BINS; i += blockDim.x) {
        int v = sh[i];
        if (v) atomicAdd(&g_hist[c * NUM_BINS + i], v);
    }
}

// ---------------------------------------------------------------------------
// Kernel 2: CDF (inclusive scan of 256 bins per channel, normalized)
//   grid = NCH, block = 256
// ---------------------------------------------------------------------------
__global__ void cdf_kernel() {
    __shared__ float s[NUM_BINS];
    const int c = blockIdx.x;
    const int t = threadIdx.x;

    s[t] = (float)g_hist[c * NUM_BINS + t];
    __syncthreads();

    // Hillis–Steele inclusive scan
    #pragma unroll
    for (int off = 1; off < NUM_BINS; off <<= 1) {
        float v = (t >= off) ? s[t - off] : 0.0f;
        __syncthreads();
        s[t] += v;
        __syncthreads();
    }

    float total = s[NUM_BINS - 1];
    g_cdf[c * NUM_BINS + t] = s[t] / fmaxf(total, 1.0f);
}

// ---------------------------------------------------------------------------
// Kernel 3: remap pixels through the per-channel CDF
//   grid = (blocksPerChan, NCH), block = 256
// ---------------------------------------------------------------------------
__global__ void remap_kernel(float* __restrict__ out) {
    __shared__ float scdf[NUM_BINS];
    const int c = blockIdx.y;

    for (int i = threadIdx.x; i < NUM_BINS; i += blockDim.x)
        scdf[i] = g_cdf[c * NUM_BINS + i];
    __syncthreads();

    const uchar4* bc = reinterpret_cast<const uchar4*>(g_bins + (size_t)c * NPIX);
    float4*       oc = reinterpret_cast<float4*>(out + (size_t)c * NPIX);

    const int stride = gridDim.x * blockDim.x;
    for (int i = blockIdx.x * blockDim.x + threadIdx.x; i < N4; i += stride) {
        uchar4 q = bc[i];
        float4 r;
        r.x = scdf[q.x];
        r.y = scdf[q.y];
        r.z = scdf[q.z];
        r.w = scdf[q.w];
        oc[i] = r;
    }
}

// ---------------------------------------------------------------------------
extern "C" void kernel_launch(void* const* d_in, const int* in_sizes, int n_in,
                              void* d_out, int out_size) {
    const float* x   = (const float*)d_in[0];
    float*       out = (float*)d_out;

    zero_hist_kernel<<<(NCH * NUM_BINS + 255) / 256, 256>>>();

    dim3 grid1(24, NCH);      // 1152 CTAs total, grid-stride within channel
    hist_kernel<<<grid1, 256>>>(x);

    cdf_kernel<<<NCH, 256>>>();

    dim3 grid3(24, NCH);
    remap_kernel<<<grid3, 256>>>(out);
}